// round 4
// baseline (speedup 1.0000x reference)
#include <cuda_runtime.h>
#include <math.h>
#include <stdint.h>

// Problem constants
#define NN 100000
#define EE 600000
#define DD 128
#define RR 4
#define GG 256
#define CC 16
#define KTOT 640   // 128 (root/h) + 4*128 (per-relation aggregates)

// ---------------- device scratch ----------------
// xa: [N, 640]; cols 0:128 = current h, cols 128+128r = aggregate of relation r
__device__ float g_xa[(size_t)NN * KTOT];            // 256 MB
__device__ float g_bth[3 * DD * KTOT];               // B hi, transposed [l][n][k]
__device__ float g_btl[3 * DD * KTOT];               // B lo
__device__ int   g_cnt[NN * RR];
__device__ int   g_rtot[RR];
__device__ int   g_rbase[RR];
__device__ int   g_rpos[RR];
__device__ int   g_eso[EE];                          // src offset (floats)
__device__ int   g_edo[EE];                          // dst offset (floats)
__device__ float g_ewt[EE];                          // 1/max(cnt,1)
__device__ float g_pool[GG * DD];
__device__ float g_pcnt[GG];

// ---------------- helpers ----------------
__device__ __forceinline__ void red_add_v4(float* addr, float x, float y, float z, float w) {
    asm volatile("red.global.add.v4.f32 [%0], {%1,%2,%3,%4};"
                 :: "l"(addr), "f"(x), "f"(y), "f"(z), "f"(w) : "memory");
}
__device__ __forceinline__ float elu1(float v) { return v > 0.0f ? v : expm1f(v); }
__device__ __forceinline__ uint32_t f2tf32(float f) {
    uint32_t u; asm("cvt.rna.tf32.f32 %0, %1;" : "=r"(u) : "f"(f)); return u;
}
__device__ __forceinline__ void mma_tf32(float* c, const uint32_t* a, uint32_t b0, uint32_t b1) {
    asm volatile("mma.sync.aligned.m16n8k8.row.col.f32.tf32.tf32.f32 "
                 "{%0,%1,%2,%3}, {%4,%5,%6,%7}, {%8,%9}, {%0,%1,%2,%3};"
                 : "+f"(c[0]), "+f"(c[1]), "+f"(c[2]), "+f"(c[3])
                 : "r"(a[0]), "r"(a[1]), "r"(a[2]), "r"(a[3]), "r"(b0), "r"(b1));
}
__device__ __forceinline__ void ldsm4(uint32_t* r, uint32_t addr) {
    asm volatile("ldmatrix.sync.aligned.m8n8.x4.shared.b16 {%0,%1,%2,%3}, [%4];"
                 : "=r"(r[0]), "=r"(r[1]), "=r"(r[2]), "=r"(r[3]) : "r"(addr));
}

// ---------------- prep kernels ----------------
__global__ void zero_misc_kernel() {
    int i = blockIdx.x * blockDim.x + threadIdx.x;
    if (i < NN * RR) g_cnt[i] = 0;
    if (i < RR)      g_rtot[i] = 0;
    if (i < GG * DD) g_pool[i] = 0.0f;
    if (i < GG)      g_pcnt[i] = 0.0f;
}

__global__ void count_kernel(const int* __restrict__ ei, const int* __restrict__ et) {
    int e = blockIdx.x * blockDim.x + threadIdx.x;
    if (e >= EE) return;
    int t = et[e];
    atomicAdd(&g_cnt[ei[EE + e] * RR + t], 1);
    atomicAdd(&g_rtot[t], 1);
}

__global__ void prefix_kernel() {
    int b = 0;
    for (int t = 0; t < RR; t++) { g_rbase[t] = b; g_rpos[t] = b; b += g_rtot[t]; }
}

__global__ void fill_kernel(const int* __restrict__ ei, const int* __restrict__ et) {
    int e = blockIdx.x * blockDim.x + threadIdx.x;
    if (e >= EE) return;
    int s = ei[e], d = ei[EE + e], t = et[e];
    int pos = atomicAdd(&g_rpos[t], 1);
    int c = g_cnt[d * RR + t];
    g_eso[pos] = s * KTOT;
    g_edo[pos] = d * KTOT + DD + t * DD;
    g_ewt[pos] = 1.0f / (float)(c > 1 ? c : 1);
}

// Build transposed split-tf32 weight matrices: Bt[l][n][k], k in [0,640)
__global__ void prepB_kernel(const float* __restrict__ root_w, const float* __restrict__ rel_w) {
    int idx = blockIdx.x * blockDim.x + threadIdx.x;
    if (idx >= 3 * KTOT * DD) return;
    int l = idx / (KTOT * DD);
    int rem = idx - l * KTOT * DD;
    int k = rem / DD;
    int n = rem - k * DD;
    float b;
    if (k < DD) b = root_w[(size_t)l * DD * DD + k * DD + n];
    else {
        int r = (k - DD) >> 7, kk = (k - DD) & 127;
        b = rel_w[(((size_t)l * RR + r) * DD + kk) * DD + n];
    }
    uint32_t hi = f2tf32(b);
    float hif = __uint_as_float(hi);
    uint32_t lo = f2tf32(b - hif);
    size_t o = (size_t)l * DD * KTOT + (size_t)n * KTOT + k;
    g_bth[o] = __uint_as_float(hi);
    g_btl[o] = __uint_as_float(lo);
}

__global__ void copyx_kernel(const float* __restrict__ x) {
    int idx = blockIdx.x * blockDim.x + threadIdx.x;
    if (idx >= NN * 32) return;
    int n = idx >> 5, c4 = (idx & 31) * 4;
    *(float4*)(g_xa + (size_t)n * KTOT + c4) = *(const float4*)(x + (size_t)n * DD + c4);
}

__global__ void zero_aggs_kernel() {
    int idx = blockIdx.x * blockDim.x + threadIdx.x;
    if (idx >= NN * 128) return;
    int n = idx >> 7, c4 = (idx & 127) * 4;
    *(float4*)(g_xa + (size_t)n * KTOT + DD + c4) = make_float4(0.f, 0.f, 0.f, 0.f);
}

// ---------------- scatter: relation-sorted edge list ----------------
__global__ __launch_bounds__(256) void scatter_kernel() {
    int e = (blockIdx.x * blockDim.x + threadIdx.x) >> 5;
    int lane = threadIdx.x & 31;
    if (e >= EE) return;
    int so = g_eso[e];
    int doff = g_edo[e];
    float w = g_ewt[e];
    const float4 v = *(const float4*)(g_xa + (size_t)so + lane * 4);
    red_add_v4(g_xa + (size_t)doff + lane * 4, v.x * w, v.y * w, v.z * w, v.w * w);
}

// ---------------- tensor-core GEMM + fused epilogue ----------------
// C[N,128] = A[N,640] x B[640,128]; A = g_xa; B split hi/lo, transposed layout.
// Block: 128(M) x 128(N), 256 threads = 8 warps (2x4; warp tile 64x32).
// mode 0: bias+BN+ELU | mode 1: bias+resid+BN+ELU | mode 2: bias+resid
__global__ __launch_bounds__(256, 1) void gemm_tc_kernel(
    const float* __restrict__ Bth, const float* __restrict__ Btl,
    const float* __restrict__ bias,
    const float* __restrict__ gamma, const float* __restrict__ beta,
    const float* __restrict__ mean, const float* __restrict__ var,
    int mode)
{
    __shared__ float As[128 * 32];
    __shared__ float Bh[128 * 32];
    __shared__ float Bl[128 * 32];

    const int tid = threadIdx.x;
    const int warp = tid >> 5, lane = tid & 31;
    const int wm = warp >> 2, wn = warp & 3;
    const int row0 = blockIdx.x * 128;
    const int grp = lane >> 3, r8 = lane & 7;

    float acc[4][4][4];
    #pragma unroll
    for (int i = 0; i < 4; i++)
        #pragma unroll
        for (int j = 0; j < 4; j++)
            #pragma unroll
            for (int k = 0; k < 4; k++) acc[i][j][k] = 0.0f;

    const uint32_t as_base = (uint32_t)__cvta_generic_to_shared(As);
    const uint32_t bh_base = (uint32_t)__cvta_generic_to_shared(Bh);
    const uint32_t bl_base = (uint32_t)__cvta_generic_to_shared(Bl);

    // ldmatrix per-thread bases
    uint32_t a_base[4]; int a_sw[4]; const int a_cs = grp >> 1;
    #pragma unroll
    for (int mt = 0; mt < 4; mt++) {
        int m = wm * 64 + mt * 16 + (grp & 1) * 8 + r8;
        a_base[mt] = as_base + m * 128;           // m * 32 floats * 4B
        a_sw[mt] = m & 7;
    }
    uint32_t bh_b[2], bl_b[2]; int b_sw[2]; const int b_cs = grp & 1;
    #pragma unroll
    for (int p = 0; p < 2; p++) {
        int n = wn * 32 + p * 16 + (grp >> 1) * 8 + r8;
        bh_b[p] = bh_base + n * 128;
        bl_b[p] = bl_base + n * 128;
        b_sw[p] = n & 7;
    }

    for (int kc = 0; kc < KTOT / 32; kc++) {
        const int k0 = kc * 32;
        // load A chunk (convert to tf32, xor-swizzled 16B chunks)
        #pragma unroll
        for (int i = 0; i < 4; i++) {
            int idx = tid + i * 256;
            int rowl = idx >> 3, kq = idx & 7;
            int grow = row0 + rowl;
            float4 v = make_float4(0.f, 0.f, 0.f, 0.f);
            if (grow < NN) v = *(const float4*)(g_xa + (size_t)grow * KTOT + k0 + kq * 4);
            uint4 u;
            u.x = f2tf32(v.x); u.y = f2tf32(v.y); u.z = f2tf32(v.z); u.w = f2tf32(v.w);
            *(uint4*)(As + rowl * 32 + ((kq ^ (rowl & 7)) << 2)) = u;
        }
        // load B hi/lo chunks (already tf32 bit patterns)
        #pragma unroll
        for (int i = 0; i < 4; i++) {
            int idx = tid + i * 256;
            int rowl = idx >> 3, kq = idx & 7;
            float4 vh = *(const float4*)(Bth + (size_t)rowl * KTOT + k0 + kq * 4);
            float4 vl = *(const float4*)(Btl + (size_t)rowl * KTOT + k0 + kq * 4);
            *(float4*)(Bh + rowl * 32 + ((kq ^ (rowl & 7)) << 2)) = vh;
            *(float4*)(Bl + rowl * 32 + ((kq ^ (rowl & 7)) << 2)) = vl;
        }
        __syncthreads();

        #pragma unroll
        for (int ks = 0; ks < 4; ks++) {
            uint32_t af[4][4], bhf[2][4], blf[2][4];
            #pragma unroll
            for (int mt = 0; mt < 4; mt++)
                ldsm4(af[mt], a_base[mt] + ((((ks << 1) + a_cs) ^ a_sw[mt]) << 4));
            #pragma unroll
            for (int p = 0; p < 2; p++) {
                int cs = (((ks << 1) + b_cs) ^ b_sw[p]) << 4;
                ldsm4(bhf[p], bh_b[p] + cs);
                ldsm4(blf[p], bl_b[p] + cs);
            }
            #pragma unroll
            for (int mt = 0; mt < 4; mt++)
                #pragma unroll
                for (int p = 0; p < 2; p++) {
                    mma_tf32(acc[mt][2 * p],     af[mt], bhf[p][0], bhf[p][1]);
                    mma_tf32(acc[mt][2 * p],     af[mt], blf[p][0], blf[p][1]);
                    mma_tf32(acc[mt][2 * p + 1], af[mt], bhf[p][2], bhf[p][3]);
                    mma_tf32(acc[mt][2 * p + 1], af[mt], blf[p][2], blf[p][3]);
                }
        }
        __syncthreads();
    }

    // fused epilogue -> write h into g_xa[:, 0:128]
    #pragma unroll
    for (int nt = 0; nt < 4; nt++) {
        int col = wn * 32 + nt * 8 + ((lane & 3) << 1);
        float b0 = bias[col], b1 = bias[col + 1];
        float g0 = 0.f, g1 = 0.f, be0 = 0.f, be1 = 0.f, mu0 = 0.f, mu1 = 0.f, rs0 = 0.f, rs1 = 0.f;
        if (mode <= 1) {
            g0 = gamma[col]; g1 = gamma[col + 1];
            be0 = beta[col]; be1 = beta[col + 1];
            mu0 = mean[col]; mu1 = mean[col + 1];
            rs0 = rsqrtf(var[col] + 1e-5f); rs1 = rsqrtf(var[col + 1] + 1e-5f);
        }
        #pragma unroll
        for (int mt = 0; mt < 4; mt++) {
            #pragma unroll
            for (int half = 0; half < 2; half++) {
                int row = row0 + wm * 64 + mt * 16 + (lane >> 2) + half * 8;
                if (row >= NN) continue;
                float v0 = acc[mt][nt][half * 2 + 0] + b0;
                float v1 = acc[mt][nt][half * 2 + 1] + b1;
                float* hp = g_xa + (size_t)row * KTOT + col;
                if (mode >= 1) { v0 += hp[0]; v1 += hp[1]; }
                if (mode <= 1) {
                    v0 = elu1((v0 - mu0) * rs0 * g0 + be0);
                    v1 = elu1((v1 - mu1) * rs1 * g1 + be1);
                }
                hp[0] = v0; hp[1] = v1;
            }
        }
    }
}

// ---------------- pooling (batch sorted; h lives in g_xa cols 0:128) ----------
__global__ __launch_bounds__(256) void pool_kernel(const int* __restrict__ batch) {
    int warp = (blockIdx.x * blockDim.x + threadIdx.x) >> 5;
    int lane = threadIdx.x & 31;
    int n0 = warp * 32;
    if (n0 >= NN) return;
    int nend = n0 + 32 < NN ? n0 + 32 : NN;

    float4 acc = make_float4(0.f, 0.f, 0.f, 0.f);
    int cur = batch[n0];
    int cnt = 0;
    for (int n = n0; n < nend; n++) {
        int b = batch[n];
        if (b != cur) {
            red_add_v4(g_pool + cur * DD + lane * 4, acc.x, acc.y, acc.z, acc.w);
            if (lane == 0) atomicAdd(&g_pcnt[cur], (float)cnt);
            acc = make_float4(0.f, 0.f, 0.f, 0.f);
            cnt = 0;
            cur = b;
        }
        float4 v = *(const float4*)(g_xa + (size_t)n * KTOT + lane * 4);
        acc.x += v.x; acc.y += v.y; acc.z += v.z; acc.w += v.w;
        cnt++;
    }
    red_add_v4(g_pool + cur * DD + lane * 4, acc.x, acc.y, acc.z, acc.w);
    if (lane == 0) atomicAdd(&g_pcnt[cur], (float)cnt);
}

// ---------------- classifier head ----------------
__global__ __launch_bounds__(64) void head_kernel(
    const float* __restrict__ W1, const float* __restrict__ b1,
    const float* __restrict__ W2, const float* __restrict__ b2,
    float* __restrict__ out)
{
    int g = blockIdx.x;
    __shared__ float p[DD];
    __shared__ float z[64];
    __shared__ float lg[CC];

    float inv = 1.0f / fmaxf(g_pcnt[g], 1.0f);
    for (int d = threadIdx.x; d < DD; d += 64) p[d] = g_pool[g * DD + d] * inv;
    __syncthreads();

    int j = threadIdx.x;
    float s = b1[j];
    #pragma unroll 4
    for (int d = 0; d < DD; d++) s += p[d] * W1[d * 64 + j];
    z[j] = elu1(s);
    __syncthreads();

    if (j < CC) {
        float t = b2[j];
        #pragma unroll 4
        for (int k = 0; k < 64; k++) t += z[k] * W2[k * CC + j];
        lg[j] = t;
    }
    __syncthreads();

    if (j < CC) {
        float m = -1e30f;
        #pragma unroll
        for (int c = 0; c < CC; c++) m = fmaxf(m, lg[c]);
        float se = 0.0f;
        #pragma unroll
        for (int c = 0; c < CC; c++) se += expf(lg[c] - m);
        out[g * CC + j] = lg[j] - m - logf(se);
    }
}

// ---------------- launch ----------------
extern "C" void kernel_launch(void* const* d_in, const int* in_sizes, int n_in,
                              void* d_out, int out_size) {
    const float* x        = (const float*)d_in[0];
    const int*   ei       = (const int*)d_in[1];
    const int*   et       = (const int*)d_in[2];
    const int*   batch    = (const int*)d_in[3];
    const float* rel_w    = (const float*)d_in[4];
    const float* root_w   = (const float*)d_in[5];
    const float* bias     = (const float*)d_in[6];
    const float* bn_gamma = (const float*)d_in[7];
    const float* bn_beta  = (const float*)d_in[8];
    const float* bn_mean  = (const float*)d_in[9];
    const float* bn_var   = (const float*)d_in[10];
    const float* cls_w1   = (const float*)d_in[11];
    const float* cls_b1   = (const float*)d_in[12];
    const float* cls_w2   = (const float*)d_in[13];
    const float* cls_b2   = (const float*)d_in[14];
    float* out = (float*)d_out;

    void* p;
    cudaGetSymbolAddress(&p, g_bth);  const float* BTH = (const float*)p;
    cudaGetSymbolAddress(&p, g_btl);  const float* BTL = (const float*)p;

    // prep
    zero_misc_kernel<<<(NN * RR + 255) / 256, 256>>>();
    count_kernel<<<(EE + 255) / 256, 256>>>(ei, et);
    prefix_kernel<<<1, 1>>>();
    fill_kernel<<<(EE + 255) / 256, 256>>>(ei, et);
    prepB_kernel<<<(3 * KTOT * DD + 255) / 256, 256>>>(root_w, rel_w);
    copyx_kernel<<<(NN * 32 + 255) / 256, 256>>>(x);

    const int zblocks = (NN * 128 + 255) / 256;
    const int sblocks = (int)(((size_t)EE * 32 + 255) / 256);
    const int gblocks = (NN + 127) / 128;
    const int pblocks = (((NN + 31) / 32) * 32 + 255) / 256;

    // layer 0
    zero_aggs_kernel<<<zblocks, 256>>>();
    scatter_kernel<<<sblocks, 256>>>();
    gemm_tc_kernel<<<gblocks, 256>>>(BTH, BTL, bias,
                                     bn_gamma, bn_beta, bn_mean, bn_var, 0);
    // layer 1
    zero_aggs_kernel<<<zblocks, 256>>>();
    scatter_kernel<<<sblocks, 256>>>();
    gemm_tc_kernel<<<gblocks, 256>>>(BTH + DD * KTOT, BTL + DD * KTOT, bias + DD,
                                     bn_gamma + DD, bn_beta + DD, bn_mean + DD, bn_var + DD, 1);
    // layer 2
    zero_aggs_kernel<<<zblocks, 256>>>();
    scatter_kernel<<<sblocks, 256>>>();
    gemm_tc_kernel<<<gblocks, 256>>>(BTH + 2 * DD * KTOT, BTL + 2 * DD * KTOT, bias + 2 * DD,
                                     bn_gamma, bn_beta, bn_mean, bn_var, 2);

    // pool + head
    pool_kernel<<<pblocks, 256>>>(batch);
    head_kernel<<<GG, 64>>>(cls_w1, cls_b1, cls_w2, cls_b2, out);
}

// round 5
// speedup vs baseline: 1.4771x; 1.4771x over previous
#include <cuda_runtime.h>
#include <math.h>
#include <stdint.h>

// Problem constants
#define NN 100000
#define EE 600000
#define DD 128
#define RR 4
#define GG 256
#define CC 16
#define KTOT 640   // 128 (h) + 4*128 (per-relation aggregates)

// ---------------- device scratch ----------------
__device__ float  g_xa[(size_t)NN * KTOT];           // [N,640] h | agg_r
__device__ float  g_bth[3 * DD * KTOT];              // B hi, transposed [l][n][k]
__device__ float  g_btl[3 * DD * KTOT];              // B lo
__device__ int    g_cnt[NN * RR];
__device__ int    g_rtot[RR];
__device__ int    g_rpos[RR];
__device__ float4 g_ep[EE];                          // {src_off, dst_off, w, 0}
__device__ float  g_pool[GG * DD];
__device__ float  g_pcnt[GG];

// ---------------- helpers ----------------
__device__ __forceinline__ void red_add_v4(float* addr, float x, float y, float z, float w) {
    asm volatile("red.global.add.v4.f32 [%0], {%1,%2,%3,%4};"
                 :: "l"(addr), "f"(x), "f"(y), "f"(z), "f"(w) : "memory");
}
__device__ __forceinline__ float elu1(float v) { return v > 0.0f ? v : expm1f(v); }
__device__ __forceinline__ uint32_t f2tf32(float f) {
    uint32_t u; asm("cvt.rna.tf32.f32 %0, %1;" : "=r"(u) : "f"(f)); return u;
}
__device__ __forceinline__ void mma_tf32(float* c, const uint32_t* a, uint32_t b0, uint32_t b1) {
    asm volatile("mma.sync.aligned.m16n8k8.row.col.f32.tf32.tf32.f32 "
                 "{%0,%1,%2,%3}, {%4,%5,%6,%7}, {%8,%9}, {%0,%1,%2,%3};"
                 : "+f"(c[0]), "+f"(c[1]), "+f"(c[2]), "+f"(c[3])
                 : "r"(a[0]), "r"(a[1]), "r"(a[2]), "r"(a[3]), "r"(b0), "r"(b1));
}
__device__ __forceinline__ void ldsm4(uint32_t* r, uint32_t addr) {
    asm volatile("ldmatrix.sync.aligned.m8n8.x4.shared.b16 {%0,%1,%2,%3}, [%4];"
                 : "=r"(r[0]), "=r"(r[1]), "=r"(r[2]), "=r"(r[3]) : "r"(addr));
}
__device__ __forceinline__ void cp16(uint32_t dst, const void* src) {
    asm volatile("cp.async.ca.shared.global [%0], [%1], 16;" :: "r"(dst), "l"(src));
}
__device__ __forceinline__ void cp_commit() { asm volatile("cp.async.commit_group;"); }
__device__ __forceinline__ void cp_wait0()  { asm volatile("cp.async.wait_group 0;"); }

// ---------------- prep kernels ----------------
__global__ void zero_misc_kernel() {
    int i = blockIdx.x * blockDim.x + threadIdx.x;
    if (i < NN * RR) g_cnt[i] = 0;
    if (i < RR)      g_rtot[i] = 0;
    if (i < GG * DD) g_pool[i] = 0.0f;
    if (i < GG)      g_pcnt[i] = 0.0f;
}

// block-aggregated relation totals + per-(dst,rel) counts
__global__ __launch_bounds__(256) void count_kernel(const int* __restrict__ ei,
                                                    const int* __restrict__ et) {
    __shared__ int h[RR];
    if (threadIdx.x < RR) h[threadIdx.x] = 0;
    __syncthreads();
    int e = blockIdx.x * blockDim.x + threadIdx.x;
    if (e < EE) {
        int t = et[e];
        atomicAdd(&g_cnt[ei[EE + e] * RR + t], 1);
        atomicAdd(&h[t], 1);
    }
    __syncthreads();
    if (threadIdx.x < RR) atomicAdd(&g_rtot[threadIdx.x], h[threadIdx.x]);
}

__global__ void prefix_kernel() {
    int b = 0;
    for (int t = 0; t < RR; t++) { g_rpos[t] = b; b += g_rtot[t]; }
}

// relation-sorted edge list via block-reserved ranges (no 4-address global storm)
__global__ __launch_bounds__(256) void fill_kernel(const int* __restrict__ ei,
                                                   const int* __restrict__ et) {
    __shared__ int h[RR], base[RR];
    if (threadIdx.x < RR) h[threadIdx.x] = 0;
    __syncthreads();
    int e = blockIdx.x * blockDim.x + threadIdx.x;
    int s = 0, d = 0, t = 0, rank = 0;
    if (e < EE) {
        s = ei[e]; d = ei[EE + e]; t = et[e];
        rank = atomicAdd(&h[t], 1);
    }
    __syncthreads();
    if (threadIdx.x < RR) base[threadIdx.x] = atomicAdd(&g_rpos[threadIdx.x], h[threadIdx.x]);
    __syncthreads();
    if (e < EE) {
        int c = g_cnt[d * RR + t];
        float w = 1.0f / (float)(c > 1 ? c : 1);
        g_ep[base[t] + rank] = make_float4(
            __int_as_float(s * KTOT),
            __int_as_float(d * KTOT + DD + t * DD),
            w, 0.0f);
    }
}

// Build transposed split-tf32 weights: Bt[l][n][k]
__global__ void prepB_kernel(const float* __restrict__ root_w, const float* __restrict__ rel_w) {
    int idx = blockIdx.x * blockDim.x + threadIdx.x;
    if (idx >= 3 * KTOT * DD) return;
    int l = idx / (KTOT * DD);
    int rem = idx - l * KTOT * DD;
    int k = rem / DD;
    int n = rem - k * DD;
    float b;
    if (k < DD) b = root_w[(size_t)l * DD * DD + k * DD + n];
    else {
        int r = (k - DD) >> 7, kk = (k - DD) & 127;
        b = rel_w[(((size_t)l * RR + r) * DD + kk) * DD + n];
    }
    uint32_t hi = f2tf32(b);
    float hif = __uint_as_float(hi);
    uint32_t lo = f2tf32(b - hif);
    size_t o = (size_t)l * DD * KTOT + (size_t)n * KTOT + k;
    g_bth[o] = __uint_as_float(hi);
    g_btl[o] = __uint_as_float(lo);
}

// init g_xa: h = x, aggs = 0 (one pass, full 640-wide rows)
__global__ void initxa_kernel(const float* __restrict__ x) {
    int idx = blockIdx.x * blockDim.x + threadIdx.x;
    if (idx >= NN * 160) return;
    int n = idx / 160, c4 = (idx - n * 160) * 4;
    float4 v = (c4 < DD) ? *(const float4*)(x + (size_t)n * DD + c4)
                         : make_float4(0.f, 0.f, 0.f, 0.f);
    *(float4*)(g_xa + (size_t)n * KTOT + c4) = v;
}

__global__ void zero_aggs_kernel() {
    int idx = blockIdx.x * blockDim.x + threadIdx.x;
    if (idx >= NN * 128) return;
    int n = idx >> 7, c4 = (idx & 127) * 4;
    *(float4*)(g_xa + (size_t)n * KTOT + DD + c4) = make_float4(0.f, 0.f, 0.f, 0.f);
}

// ---------------- scatter: relation-sorted, packed edge records ----------------
__global__ __launch_bounds__(256) void scatter_kernel() {
    int e = (blockIdx.x * blockDim.x + threadIdx.x) >> 5;
    int lane = threadIdx.x & 31;
    if (e >= EE) return;
    float4 pk = g_ep[e];
    int so  = __float_as_int(pk.x);
    int doo = __float_as_int(pk.y);
    float w = pk.z;
    const float4 v = *(const float4*)(g_xa + (size_t)so + lane * 4);
    red_add_v4(g_xa + (size_t)doo + lane * 4, v.x * w, v.y * w, v.z * w, v.w * w);
}

// ---------------- tensor-core GEMM, cp.async double-buffered, fused epilogue ----
// C[N,128] = A[N,640] x B[640,128]; block 128x128, 8 warps (2x4), warp 64x32.
// mode 0: bias+BN+ELU | 1: bias+resid+BN+ELU | 2: bias+resid
__global__ __launch_bounds__(256, 1) void gemm_tc_kernel(
    const float* __restrict__ Bth, const float* __restrict__ Btl,
    const float* __restrict__ bias,
    const float* __restrict__ gamma, const float* __restrict__ beta,
    const float* __restrict__ mean, const float* __restrict__ var,
    int mode)
{
    extern __shared__ float sm[];
    float* As  = sm;                 // [2][4096]
    float* Bhs = sm + 8192;          // [2][4096]
    float* Bls = sm + 16384;         // [2][4096]

    const int tid = threadIdx.x;
    const int warp = tid >> 5, lane = tid & 31;
    const int wm = warp >> 2, wn = warp & 3;
    const int row0 = blockIdx.x * 128;
    const int grp = lane >> 3, r8 = lane & 7;

    float acc[4][4][4];
    #pragma unroll
    for (int i = 0; i < 4; i++)
        #pragma unroll
        for (int j = 0; j < 4; j++)
            #pragma unroll
            for (int k = 0; k < 4; k++) acc[i][j][k] = 0.0f;

    const uint32_t as_base = (uint32_t)__cvta_generic_to_shared(As);
    const uint32_t bh_base = (uint32_t)__cvta_generic_to_shared(Bhs);
    const uint32_t bl_base = (uint32_t)__cvta_generic_to_shared(Bls);

    // ldmatrix per-thread bases (buffer offset added at use: +buf*16384 bytes)
    uint32_t a_base[4]; int a_sw[4]; const int a_cs = grp >> 1;
    #pragma unroll
    for (int mt = 0; mt < 4; mt++) {
        int m = wm * 64 + mt * 16 + (grp & 1) * 8 + r8;
        a_base[mt] = as_base + m * 128;
        a_sw[mt] = m & 7;
    }
    uint32_t bh_b[2], bl_b[2]; int b_sw[2]; const int b_cs = grp & 1;
    #pragma unroll
    for (int p = 0; p < 2; p++) {
        int n = wn * 32 + p * 16 + (grp >> 1) * 8 + r8;
        bh_b[p] = bh_base + n * 128;
        bl_b[p] = bl_base + n * 128;
        b_sw[p] = n & 7;
    }

    // loader geometry: per thread kq fixed, 4 rows strided by 32
    const int kq   = tid & 7;
    const int rl0  = tid >> 3;                 // 0..31
    const int swf  = (kq ^ (rl0 & 7)) << 2;    // float offset within row
    float4 areg[4];

    #define LDGA(kc) {                                                        \
        int _k0 = (kc) * 32;                                                  \
        _Pragma("unroll")                                                     \
        for (int i = 0; i < 4; i++) {                                         \
            int rowl = rl0 + 32 * i;                                          \
            int grow = row0 + rowl;                                           \
            areg[i] = (grow < NN)                                             \
                ? *(const float4*)(g_xa + (size_t)grow * KTOT + _k0 + kq * 4) \
                : make_float4(0.f, 0.f, 0.f, 0.f);                            \
        }                                                                     \
    }
    #define STSA(b) {                                                         \
        _Pragma("unroll")                                                     \
        for (int i = 0; i < 4; i++) {                                         \
            int rowl = rl0 + 32 * i;                                          \
            uint4 u;                                                          \
            u.x = f2tf32(areg[i].x); u.y = f2tf32(areg[i].y);                 \
            u.z = f2tf32(areg[i].z); u.w = f2tf32(areg[i].w);                 \
            *(uint4*)(As + (b) * 4096 + rowl * 32 + swf) = u;                 \
        }                                                                     \
    }
    #define CPB(kc, b) {                                                      \
        int _k0 = (kc) * 32;                                                  \
        _Pragma("unroll")                                                     \
        for (int i = 0; i < 4; i++) {                                         \
            int rowl = rl0 + 32 * i;                                          \
            uint32_t off = (b) * 16384u + rowl * 128u + (uint32_t)(swf * 4);  \
            cp16(bh_base + off, Bth + (size_t)rowl * KTOT + _k0 + kq * 4);    \
            cp16(bl_base + off, Btl + (size_t)rowl * KTOT + _k0 + kq * 4);    \
        }                                                                     \
    }
    #define COMPUTE(b) {                                                      \
        uint32_t bo = (b) * 16384u;                                           \
        _Pragma("unroll")                                                     \
        for (int ks = 0; ks < 4; ks++) {                                      \
            uint32_t af[4][4], bhf[2][4], blf[2][4];                          \
            _Pragma("unroll")                                                 \
            for (int mt = 0; mt < 4; mt++)                                    \
                ldsm4(af[mt], a_base[mt] + bo +                               \
                      ((((ks << 1) + a_cs) ^ a_sw[mt]) << 4));                \
            _Pragma("unroll")                                                 \
            for (int p = 0; p < 2; p++) {                                     \
                int cs = (((ks << 1) + b_cs) ^ b_sw[p]) << 4;                 \
                ldsm4(bhf[p], bh_b[p] + bo + cs);                             \
                ldsm4(blf[p], bl_b[p] + bo + cs);                             \
            }                                                                 \
            _Pragma("unroll")                                                 \
            for (int mt = 0; mt < 4; mt++)                                    \
                _Pragma("unroll")                                             \
                for (int p = 0; p < 2; p++) {                                 \
                    mma_tf32(acc[mt][2*p],   af[mt], bhf[p][0], bhf[p][1]);   \
                    mma_tf32(acc[mt][2*p],   af[mt], blf[p][0], blf[p][1]);   \
                    mma_tf32(acc[mt][2*p+1], af[mt], bhf[p][2], bhf[p][3]);   \
                    mma_tf32(acc[mt][2*p+1], af[mt], blf[p][2], blf[p][3]);   \
                }                                                             \
        }                                                                     \
    }

    // prologue: stage 0
    LDGA(0);
    CPB(0, 0); cp_commit();
    STSA(0);
    cp_wait0();
    __syncthreads();

    int buf = 0;
    for (int kc = 0; kc < KTOT / 32; kc++) {
        if (kc < KTOT / 32 - 1) {
            LDGA(kc + 1);
            CPB(kc + 1, buf ^ 1); cp_commit();
        }
        COMPUTE(buf);
        if (kc < KTOT / 32 - 1) {
            STSA(buf ^ 1);
            cp_wait0();
        }
        __syncthreads();
        buf ^= 1;
    }

    // fused epilogue -> write h into g_xa[:, 0:128]
    #pragma unroll
    for (int nt = 0; nt < 4; nt++) {
        int col = wn * 32 + nt * 8 + ((lane & 3) << 1);
        float b0 = bias[col], b1 = bias[col + 1];
        float g0 = 0.f, g1 = 0.f, be0 = 0.f, be1 = 0.f, mu0 = 0.f, mu1 = 0.f, rs0 = 0.f, rs1 = 0.f;
        if (mode <= 1) {
            g0 = gamma[col]; g1 = gamma[col + 1];
            be0 = beta[col]; be1 = beta[col + 1];
            mu0 = mean[col]; mu1 = mean[col + 1];
            rs0 = rsqrtf(var[col] + 1e-5f); rs1 = rsqrtf(var[col + 1] + 1e-5f);
        }
        #pragma unroll
        for (int mt = 0; mt < 4; mt++) {
            #pragma unroll
            for (int half = 0; half < 2; half++) {
                int row = row0 + wm * 64 + mt * 16 + (lane >> 2) + half * 8;
                if (row >= NN) continue;
                float v0 = acc[mt][nt][half * 2 + 0] + b0;
                float v1 = acc[mt][nt][half * 2 + 1] + b1;
                float* hp = g_xa + (size_t)row * KTOT + col;
                if (mode >= 1) { v0 += hp[0]; v1 += hp[1]; }
                if (mode <= 1) {
                    v0 = elu1((v0 - mu0) * rs0 * g0 + be0);
                    v1 = elu1((v1 - mu1) * rs1 * g1 + be1);
                }
                hp[0] = v0; hp[1] = v1;
            }
        }
    }
    #undef LDGA
    #undef STSA
    #undef CPB
    #undef COMPUTE
}

// ---------------- pooling (batch sorted) ----------------
__global__ __launch_bounds__(256) void pool_kernel(const int* __restrict__ batch) {
    int warp = (blockIdx.x * blockDim.x + threadIdx.x) >> 5;
    int lane = threadIdx.x & 31;
    int n0 = warp * 32;
    if (n0 >= NN) return;
    int nend = n0 + 32 < NN ? n0 + 32 : NN;

    float4 acc = make_float4(0.f, 0.f, 0.f, 0.f);
    int cur = batch[n0];
    int cnt = 0;
    for (int n = n0; n < nend; n++) {
        int b = batch[n];
        if (b != cur) {
            red_add_v4(g_pool + cur * DD + lane * 4, acc.x, acc.y, acc.z, acc.w);
            if (lane == 0) atomicAdd(&g_pcnt[cur], (float)cnt);
            acc = make_float4(0.f, 0.f, 0.f, 0.f);
            cnt = 0;
            cur = b;
        }
        float4 v = *(const float4*)(g_xa + (size_t)n * KTOT + lane * 4);
        acc.x += v.x; acc.y += v.y; acc.z += v.z; acc.w += v.w;
        cnt++;
    }
    red_add_v4(g_pool + cur * DD + lane * 4, acc.x, acc.y, acc.z, acc.w);
    if (lane == 0) atomicAdd(&g_pcnt[cur], (float)cnt);
}

// ---------------- classifier head ----------------
__global__ __launch_bounds__(64) void head_kernel(
    const float* __restrict__ W1, const float* __restrict__ b1,
    const float* __restrict__ W2, const float* __restrict__ b2,
    float* __restrict__ out)
{
    int g = blockIdx.x;
    __shared__ float p[DD];
    __shared__ float z[64];
    __shared__ float lg[CC];

    float inv = 1.0f / fmaxf(g_pcnt[g], 1.0f);
    for (int d = threadIdx.x; d < DD; d += 64) p[d] = g_pool[g * DD + d] * inv;
    __syncthreads();

    int j = threadIdx.x;
    float s = b1[j];
    #pragma unroll 4
    for (int d = 0; d < DD; d++) s += p[d] * W1[d * 64 + j];
    z[j] = elu1(s);
    __syncthreads();

    if (j < CC) {
        float t = b2[j];
        #pragma unroll 4
        for (int k = 0; k < 64; k++) t += z[k] * W2[k * CC + j];
        lg[j] = t;
    }
    __syncthreads();

    if (j < CC) {
        float m = -1e30f;
        #pragma unroll
        for (int c = 0; c < CC; c++) m = fmaxf(m, lg[c]);
        float se = 0.0f;
        #pragma unroll
        for (int c = 0; c < CC; c++) se += expf(lg[c] - m);
        out[g * CC + j] = lg[j] - m - logf(se);
    }
}

// ---------------- launch ----------------
extern "C" void kernel_launch(void* const* d_in, const int* in_sizes, int n_in,
                              void* d_out, int out_size) {
    const float* x        = (const float*)d_in[0];
    const int*   ei       = (const int*)d_in[1];
    const int*   et       = (const int*)d_in[2];
    const int*   batch    = (const int*)d_in[3];
    const float* rel_w    = (const float*)d_in[4];
    const float* root_w   = (const float*)d_in[5];
    const float* bias     = (const float*)d_in[6];
    const float* bn_gamma = (const float*)d_in[7];
    const float* bn_beta  = (const float*)d_in[8];
    const float* bn_mean  = (const float*)d_in[9];
    const float* bn_var   = (const float*)d_in[10];
    const float* cls_w1   = (const float*)d_in[11];
    const float* cls_b1   = (const float*)d_in[12];
    const float* cls_w2   = (const float*)d_in[13];
    const float* cls_b2   = (const float*)d_in[14];
    float* out = (float*)d_out;

    static int smem_set = 0;
    if (!smem_set) {
        cudaFuncSetAttribute(gemm_tc_kernel,
                             cudaFuncAttributeMaxDynamicSharedMemorySize, 98304);
        smem_set = 1;
    }

    void* p;
    cudaGetSymbolAddress(&p, g_bth);  const float* BTH = (const float*)p;
    cudaGetSymbolAddress(&p, g_btl);  const float* BTL = (const float*)p;

    // prep
    zero_misc_kernel<<<(NN * RR + 255) / 256, 256>>>();
    count_kernel<<<(EE + 255) / 256, 256>>>(ei, et);
    prefix_kernel<<<1, 1>>>();
    fill_kernel<<<(EE + 255) / 256, 256>>>(ei, et);
    prepB_kernel<<<(3 * KTOT * DD + 255) / 256, 256>>>(root_w, rel_w);
    initxa_kernel<<<(NN * 160 + 255) / 256, 256>>>(x);

    const int zblocks = (NN * 128 + 255) / 256;
    const int sblocks = (int)(((size_t)EE * 32 + 255) / 256);
    const int gblocks = (NN + 127) / 128;
    const int pblocks = (((NN + 31) / 32) * 32 + 255) / 256;
    const size_t smem = 98304;

    // layer 0
    scatter_kernel<<<sblocks, 256>>>();
    gemm_tc_kernel<<<gblocks, 256, smem>>>(BTH, BTL, bias,
                                           bn_gamma, bn_beta, bn_mean, bn_var, 0);
    // layer 1
    zero_aggs_kernel<<<zblocks, 256>>>();
    scatter_kernel<<<sblocks, 256>>>();
    gemm_tc_kernel<<<gblocks, 256, smem>>>(BTH + DD * KTOT, BTL + DD * KTOT, bias + DD,
                                           bn_gamma + DD, bn_beta + DD, bn_mean + DD,
                                           bn_var + DD, 1);
    // layer 2
    zero_aggs_kernel<<<zblocks, 256>>>();
    scatter_kernel<<<sblocks, 256>>>();
    gemm_tc_kernel<<<gblocks, 256, smem>>>(BTH + 2 * DD * KTOT, BTL + 2 * DD * KTOT,
                                           bias + 2 * DD,
                                           bn_gamma, bn_beta, bn_mean, bn_var, 2);

    // pool + head
    pool_kernel<<<pblocks, 256>>>(batch);
    head_kernel<<<GG, 64>>>(cls_w1, cls_b1, cls_w2, cls_b2, out);
}

// round 6
// speedup vs baseline: 1.5257x; 1.0329x over previous
#include <cuda_runtime.h>
#include <cuda_bf16.h>
#include <math.h>
#include <stdint.h>

// Problem constants
#define NN 100000
#define EE 600000
#define DD 128
#define RR 4
#define GG 256
#define CC 16
#define KTOT 640   // 128 (h) + 4*128 (per-relation aggregates)

// ---------------- device scratch ----------------
__device__ float          g_xa[(size_t)NN * KTOT];   // [N,640] h | agg_r
__device__ __nv_bfloat16  g_bh[3 * DD * KTOT];       // B hi bf16, transposed [l][n][k]
__device__ __nv_bfloat16  g_bl[3 * DD * KTOT];       // B lo bf16
__device__ int    g_cnt[NN * RR];
__device__ int    g_rtot[RR];
__device__ int    g_rpos[RR];
__device__ float4 g_ep[EE];                          // {src_off, dst_off, w, 0}
__device__ float  g_pool[GG * DD];
__device__ float  g_pcnt[GG];

// ---------------- helpers ----------------
__device__ __forceinline__ void red_add_v4(float* addr, float x, float y, float z, float w) {
    asm volatile("red.global.add.v4.f32 [%0], {%1,%2,%3,%4};"
                 :: "l"(addr), "f"(x), "f"(y), "f"(z), "f"(w) : "memory");
}
__device__ __forceinline__ float elu1(float v) { return v > 0.0f ? v : expm1f(v); }
__device__ __forceinline__ float bf16_round(float v) {
    return __bfloat162float(__float2bfloat16_rn(v));
}
// pack {lo, hi} little-endian: lower 16 bits = bf16(lo)
__device__ __forceinline__ uint32_t pack_bf16x2(float lo, float hi) {
    uint32_t r;
    asm("cvt.rn.bf16x2.f32 %0, %1, %2;" : "=r"(r) : "f"(hi), "f"(lo));
    return r;
}
__device__ __forceinline__ void mma_bf16(float* c, const uint32_t* a, uint32_t b0, uint32_t b1) {
    asm volatile("mma.sync.aligned.m16n8k16.row.col.f32.bf16.bf16.f32 "
                 "{%0,%1,%2,%3}, {%4,%5,%6,%7}, {%8,%9}, {%0,%1,%2,%3};"
                 : "+f"(c[0]), "+f"(c[1]), "+f"(c[2]), "+f"(c[3])
                 : "r"(a[0]), "r"(a[1]), "r"(a[2]), "r"(a[3]), "r"(b0), "r"(b1));
}
__device__ __forceinline__ void ldsm4(uint32_t* r, uint32_t addr) {
    asm volatile("ldmatrix.sync.aligned.m8n8.x4.shared.b16 {%0,%1,%2,%3}, [%4];"
                 : "=r"(r[0]), "=r"(r[1]), "=r"(r[2]), "=r"(r[3]) : "r"(addr));
}
__device__ __forceinline__ void cp16(uint32_t dst, const void* src) {
    asm volatile("cp.async.ca.shared.global [%0], [%1], 16;" :: "r"(dst), "l"(src));
}
__device__ __forceinline__ void cp_commit() { asm volatile("cp.async.commit_group;"); }
__device__ __forceinline__ void cp_wait0()  { asm volatile("cp.async.wait_group 0;"); }

// ---------------- prep kernels ----------------
__global__ void zero_misc_kernel() {
    int i = blockIdx.x * blockDim.x + threadIdx.x;
    if (i < NN * RR) g_cnt[i] = 0;
    if (i < RR)      g_rtot[i] = 0;
    if (i < GG * DD) g_pool[i] = 0.0f;
    if (i < GG)      g_pcnt[i] = 0.0f;
}

__global__ __launch_bounds__(256) void count_kernel(const int* __restrict__ ei,
                                                    const int* __restrict__ et) {
    __shared__ int h[RR];
    if (threadIdx.x < RR) h[threadIdx.x] = 0;
    __syncthreads();
    int e = blockIdx.x * blockDim.x + threadIdx.x;
    if (e < EE) {
        int t = et[e];
        atomicAdd(&g_cnt[ei[EE + e] * RR + t], 1);
        atomicAdd(&h[t], 1);
    }
    __syncthreads();
    if (threadIdx.x < RR) atomicAdd(&g_rtot[threadIdx.x], h[threadIdx.x]);
}

__global__ void prefix_kernel() {
    int b = 0;
    for (int t = 0; t < RR; t++) { g_rpos[t] = b; b += g_rtot[t]; }
}

__global__ __launch_bounds__(256) void fill_kernel(const int* __restrict__ ei,
                                                   const int* __restrict__ et) {
    __shared__ int h[RR], base[RR];
    if (threadIdx.x < RR) h[threadIdx.x] = 0;
    __syncthreads();
    int e = blockIdx.x * blockDim.x + threadIdx.x;
    int s = 0, d = 0, t = 0, rank = 0;
    if (e < EE) {
        s = ei[e]; d = ei[EE + e]; t = et[e];
        rank = atomicAdd(&h[t], 1);
    }
    __syncthreads();
    if (threadIdx.x < RR) base[threadIdx.x] = atomicAdd(&g_rpos[threadIdx.x], h[threadIdx.x]);
    __syncthreads();
    if (e < EE) {
        int c = g_cnt[d * RR + t];
        float w = 1.0f / (float)(c > 1 ? c : 1);
        g_ep[base[t] + rank] = make_float4(
            __int_as_float(s * KTOT),
            __int_as_float(d * KTOT + DD + t * DD),
            w, 0.0f);
    }
}

// Build transposed split-bf16 weights: Bt[l][n][k]
__global__ void prepB_kernel(const float* __restrict__ root_w, const float* __restrict__ rel_w) {
    int idx = blockIdx.x * blockDim.x + threadIdx.x;
    if (idx >= 3 * KTOT * DD) return;
    int l = idx / (KTOT * DD);
    int rem = idx - l * KTOT * DD;
    int k = rem / DD;
    int n = rem - k * DD;
    float b;
    if (k < DD) b = root_w[(size_t)l * DD * DD + k * DD + n];
    else {
        int r = (k - DD) >> 7, kk = (k - DD) & 127;
        b = rel_w[(((size_t)l * RR + r) * DD + kk) * DD + n];
    }
    __nv_bfloat16 hi = __float2bfloat16_rn(b);
    __nv_bfloat16 lo = __float2bfloat16_rn(b - __bfloat162float(hi));
    size_t o = (size_t)l * DD * KTOT + (size_t)n * KTOT + k;
    g_bh[o] = hi;
    g_bl[o] = lo;
}

// init g_xa: h = x, aggs = 0
__global__ void initxa_kernel(const float* __restrict__ x) {
    int idx = blockIdx.x * blockDim.x + threadIdx.x;
    if (idx >= NN * 160) return;
    int n = idx / 160, c4 = (idx - n * 160) * 4;
    float4 v = (c4 < DD) ? *(const float4*)(x + (size_t)n * DD + c4)
                         : make_float4(0.f, 0.f, 0.f, 0.f);
    *(float4*)(g_xa + (size_t)n * KTOT + c4) = v;
}

// ---------------- scatter: relation-sorted, packed edge records ----------------
__global__ __launch_bounds__(256) void scatter_kernel() {
    int e = (blockIdx.x * blockDim.x + threadIdx.x) >> 5;
    int lane = threadIdx.x & 31;
    if (e >= EE) return;
    float4 pk = g_ep[e];
    int so  = __float_as_int(pk.x);
    int doo = __float_as_int(pk.y);
    float w = pk.z;
    const float4 v = *(const float4*)(g_xa + (size_t)so + lane * 4);
    red_add_v4(g_xa + (size_t)doo + lane * 4, v.x * w, v.y * w, v.z * w, v.w * w);
}

// ---------------- bf16 3-term tensor-core GEMM, double-buffered, fused epilogue ----
// C[N,128] = A[N,640] x B[640,128];  C ≈ Ah·Bh + Ah·Bl + Al·Bh  (bf16 splits)
// Block 128x128, 8 warps (2x4), warp tile 64x32, k-chunk 32 (2 x k16).
// Smem rows padded to 80B: addr/16 mod 8 = (5r + c) mod 8 -> conflict-free ldmatrix.
// mode 0: bias+BN+ELU | 1: bias+resid+BN+ELU | 2: bias+resid
// zero_next: also zero this block's agg columns (128:640) for the next scatter.
#define STG_STRIDE 10240          // 128 rows * 80B per stage
#define AH_OFF 0
#define AL_OFF 20480
#define BH_OFF 40960
#define BL_OFF 61440
#define SMEM_BYTES 81920

__global__ __launch_bounds__(256) void gemm_tc_kernel(
    const __nv_bfloat16* __restrict__ Bhg, const __nv_bfloat16* __restrict__ Blg,
    const float* __restrict__ bias,
    const float* __restrict__ gamma, const float* __restrict__ beta,
    const float* __restrict__ mean, const float* __restrict__ var,
    int mode, int zero_next)
{
    extern __shared__ char smc[];
    const uint32_t smb = (uint32_t)__cvta_generic_to_shared(smc);

    const int tid = threadIdx.x;
    const int warp = tid >> 5, lane = tid & 31;
    const int wm = warp >> 2, wn = warp & 3;
    const int row0 = blockIdx.x * 128;

    float acc[4][4][4];
    #pragma unroll
    for (int i = 0; i < 4; i++)
        #pragma unroll
        for (int j = 0; j < 4; j++)
            #pragma unroll
            for (int k = 0; k < 4; k++) acc[i][j][k] = 0.0f;

    // ---- per-thread ldmatrix base addresses ----
    // A x4: lane l -> row m_base + (l&15), k8-chunk (l>>4)
    uint32_t a_addr[4];
    #pragma unroll
    for (int mt = 0; mt < 4; mt++) {
        int m = wm * 64 + mt * 16 + (lane & 15);
        a_addr[mt] = smb + AH_OFF + m * 80 + (lane >> 4) * 16;
    }
    // B x4: lane l -> row n_base + (l&7) + (l>>4)*8, k8-chunk (l>>3)&1
    uint32_t b_addr[2];
    #pragma unroll
    for (int p = 0; p < 2; p++) {
        int n = wn * 32 + p * 16 + (lane & 7) + (lane >> 4) * 8;
        b_addr[p] = smb + BH_OFF + n * 80 + ((lane >> 3) & 1) * 16;
    }

    // ---- loader geometry: c = k8-chunk (0..3), r = row (0..63), rows r & r+64 ----
    const int lc = tid & 3;
    const int lr = tid >> 2;
    float4 areg[4];   // 2 rows x 8 floats

    #define LDGA(kc) {                                                           \
        int _k0 = (kc) * 32 + lc * 8;                                            \
        _Pragma("unroll")                                                        \
        for (int i = 0; i < 2; i++) {                                            \
            int grow = row0 + lr + 64 * i;                                       \
            if (grow < NN) {                                                     \
                areg[2*i]   = *(const float4*)(g_xa + (size_t)grow * KTOT + _k0);     \
                areg[2*i+1] = *(const float4*)(g_xa + (size_t)grow * KTOT + _k0 + 4); \
            } else {                                                             \
                areg[2*i] = areg[2*i+1] = make_float4(0.f, 0.f, 0.f, 0.f);       \
            }                                                                    \
        }                                                                        \
    }
    #define STSA(b) {                                                            \
        _Pragma("unroll")                                                        \
        for (int i = 0; i < 2; i++) {                                            \
            float4 v0 = areg[2*i], v1 = areg[2*i+1];                             \
            uint4 uh;                                                            \
            uh.x = pack_bf16x2(v0.x, v0.y);                                      \
            uh.y = pack_bf16x2(v0.z, v0.w);                                      \
            uh.z = pack_bf16x2(v1.x, v1.y);                                      \
            uh.w = pack_bf16x2(v1.z, v1.w);                                      \
            uint4 ul;                                                            \
            ul.x = pack_bf16x2(v0.x - bf16_round(v0.x), v0.y - bf16_round(v0.y));\
            ul.y = pack_bf16x2(v0.z - bf16_round(v0.z), v0.w - bf16_round(v0.w));\
            ul.z = pack_bf16x2(v1.x - bf16_round(v1.x), v1.y - bf16_round(v1.y));\
            ul.w = pack_bf16x2(v1.z - bf16_round(v1.z), v1.w - bf16_round(v1.w));\
            uint32_t off = (lr + 64*i) * 80u + lc * 16u + (b) * STG_STRIDE;      \
            *(uint4*)(smc + AH_OFF + off) = uh;                                  \
            *(uint4*)(smc + AL_OFF + off) = ul;                                  \
        }                                                                        \
    }
    #define CPB(kc, b) {                                                         \
        int _k0 = (kc) * 32 + lc * 8;                                            \
        _Pragma("unroll")                                                        \
        for (int i = 0; i < 2; i++) {                                            \
            int n = lr + 64 * i;                                                 \
            uint32_t off = n * 80u + lc * 16u + (b) * STG_STRIDE;                \
            cp16(smb + BH_OFF + off, Bhg + (size_t)n * KTOT + _k0);              \
            cp16(smb + BL_OFF + off, Blg + (size_t)n * KTOT + _k0);              \
        }                                                                        \
    }
    #define COMPUTE(b) {                                                         \
        uint32_t bo = (b) * (uint32_t)STG_STRIDE;                                \
        _Pragma("unroll")                                                        \
        for (int ks = 0; ks < 2; ks++) {                                         \
            uint32_t ah[4][4], al[4][4], bh[2][4], bl[2][4];                     \
            _Pragma("unroll")                                                    \
            for (int mt = 0; mt < 4; mt++) {                                     \
                ldsm4(ah[mt], a_addr[mt] + bo + ks * 32);                        \
                ldsm4(al[mt], a_addr[mt] + (AL_OFF - AH_OFF) + bo + ks * 32);    \
            }                                                                    \
            _Pragma("unroll")                                                    \
            for (int p = 0; p < 2; p++) {                                        \
                ldsm4(bh[p], b_addr[p] + bo + ks * 32);                          \
                ldsm4(bl[p], b_addr[p] + (BL_OFF - BH_OFF) + bo + ks * 32);      \
            }                                                                    \
            _Pragma("unroll")                                                    \
            for (int mt = 0; mt < 4; mt++)                                       \
                _Pragma("unroll")                                                \
                for (int nt = 0; nt < 4; nt++) {                                 \
                    int p = nt >> 1, ix = (nt & 1) * 2;                          \
                    mma_bf16(acc[mt][nt], ah[mt], bh[p][ix], bh[p][ix+1]);       \
                    mma_bf16(acc[mt][nt], ah[mt], bl[p][ix], bl[p][ix+1]);       \
                    mma_bf16(acc[mt][nt], al[mt], bh[p][ix], bh[p][ix+1]);       \
                }                                                                \
        }                                                                        \
    }

    // prologue
    LDGA(0);
    CPB(0, 0); cp_commit();
    STSA(0);
    cp_wait0();
    __syncthreads();

    int buf = 0;
    #pragma unroll 1
    for (int kc = 0; kc < KTOT / 32; kc++) {
        if (kc < KTOT / 32 - 1) {
            LDGA(kc + 1);
            CPB(kc + 1, buf ^ 1); cp_commit();
        }
        COMPUTE(buf);
        if (kc < KTOT / 32 - 1) {
            STSA(buf ^ 1);
            cp_wait0();
        }
        __syncthreads();
        buf ^= 1;
    }

    // fused epilogue -> write h into g_xa[:, 0:128]
    #pragma unroll
    for (int nt = 0; nt < 4; nt++) {
        int col = wn * 32 + nt * 8 + ((lane & 3) << 1);
        float b0 = bias[col], b1 = bias[col + 1];
        float g0 = 0.f, g1 = 0.f, be0 = 0.f, be1 = 0.f, mu0 = 0.f, mu1 = 0.f, rs0 = 0.f, rs1 = 0.f;
        if (mode <= 1) {
            g0 = gamma[col]; g1 = gamma[col + 1];
            be0 = beta[col]; be1 = beta[col + 1];
            mu0 = mean[col]; mu1 = mean[col + 1];
            rs0 = rsqrtf(var[col] + 1e-5f); rs1 = rsqrtf(var[col + 1] + 1e-5f);
        }
        #pragma unroll
        for (int mt = 0; mt < 4; mt++) {
            #pragma unroll
            for (int half = 0; half < 2; half++) {
                int row = row0 + wm * 64 + mt * 16 + (lane >> 2) + half * 8;
                if (row >= NN) continue;
                float v0 = acc[mt][nt][half * 2 + 0] + b0;
                float v1 = acc[mt][nt][half * 2 + 1] + b1;
                float* hp = g_xa + (size_t)row * KTOT + col;
                if (mode >= 1) { v0 += hp[0]; v1 += hp[1]; }
                if (mode <= 1) {
                    v0 = elu1((v0 - mu0) * rs0 * g0 + be0);
                    v1 = elu1((v1 - mu1) * rs1 * g1 + be1);
                }
                hp[0] = v0; hp[1] = v1;
            }
        }
    }

    // fused agg-zeroing for next layer's scatter (own rows only)
    if (zero_next) {
        #pragma unroll 4
        for (int it = 0; it < 64; it++) {
            int idx = tid + it * 256;          // 0..16383
            int rowl = idx >> 7, q = idx & 127;
            int row = row0 + rowl;
            if (row < NN)
                *(float4*)(g_xa + (size_t)row * KTOT + DD + q * 4) =
                    make_float4(0.f, 0.f, 0.f, 0.f);
        }
    }
    #undef LDGA
    #undef STSA
    #undef CPB
    #undef COMPUTE
}

// ---------------- pooling (batch sorted) ----------------
__global__ __launch_bounds__(256) void pool_kernel(const int* __restrict__ batch) {
    int warp = (blockIdx.x * blockDim.x + threadIdx.x) >> 5;
    int lane = threadIdx.x & 31;
    int n0 = warp * 32;
    if (n0 >= NN) return;
    int nend = n0 + 32 < NN ? n0 + 32 : NN;

    float4 acc = make_float4(0.f, 0.f, 0.f, 0.f);
    int cur = batch[n0];
    int cnt = 0;
    for (int n = n0; n < nend; n++) {
        int b = batch[n];
        if (b != cur) {
            red_add_v4(g_pool + cur * DD + lane * 4, acc.x, acc.y, acc.z, acc.w);
            if (lane == 0) atomicAdd(&g_pcnt[cur], (float)cnt);
            acc = make_float4(0.f, 0.f, 0.f, 0.f);
            cnt = 0;
            cur = b;
        }
        float4 v = *(const float4*)(g_xa + (size_t)n * KTOT + lane * 4);
        acc.x += v.x; acc.y += v.y; acc.z += v.z; acc.w += v.w;
        cnt++;
    }
    red_add_v4(g_pool + cur * DD + lane * 4, acc.x, acc.y, acc.z, acc.w);
    if (lane == 0) atomicAdd(&g_pcnt[cur], (float)cnt);
}

// ---------------- classifier head ----------------
__global__ __launch_bounds__(64) void head_kernel(
    const float* __restrict__ W1, const float* __restrict__ b1,
    const float* __restrict__ W2, const float* __restrict__ b2,
    float* __restrict__ out)
{
    int g = blockIdx.x;
    __shared__ float p[DD];
    __shared__ float z[64];
    __shared__ float lg[CC];

    float inv = 1.0f / fmaxf(g_pcnt[g], 1.0f);
    for (int d = threadIdx.x; d < DD; d += 64) p[d] = g_pool[g * DD + d] * inv;
    __syncthreads();

    int j = threadIdx.x;
    float s = b1[j];
    #pragma unroll 4
    for (int d = 0; d < DD; d++) s += p[d] * W1[d * 64 + j];
    z[j] = elu1(s);
    __syncthreads();

    if (j < CC) {
        float t = b2[j];
        #pragma unroll 4
        for (int k = 0; k < 64; k++) t += z[k] * W2[k * CC + j];
        lg[j] = t;
    }
    __syncthreads();

    if (j < CC) {
        float m = -1e30f;
        #pragma unroll
        for (int c = 0; c < CC; c++) m = fmaxf(m, lg[c]);
        float se = 0.0f;
        #pragma unroll
        for (int c = 0; c < CC; c++) se += expf(lg[c] - m);
        out[g * CC + j] = lg[j] - m - logf(se);
    }
}

// ---------------- launch ----------------
extern "C" void kernel_launch(void* const* d_in, const int* in_sizes, int n_in,
                              void* d_out, int out_size) {
    const float* x        = (const float*)d_in[0];
    const int*   ei       = (const int*)d_in[1];
    const int*   et       = (const int*)d_in[2];
    const int*   batch    = (const int*)d_in[3];
    const float* rel_w    = (const float*)d_in[4];
    const float* root_w   = (const float*)d_in[5];
    const float* bias     = (const float*)d_in[6];
    const float* bn_gamma = (const float*)d_in[7];
    const float* bn_beta  = (const float*)d_in[8];
    const float* bn_mean  = (const float*)d_in[9];
    const float* bn_var   = (const float*)d_in[10];
    const float* cls_w1   = (const float*)d_in[11];
    const float* cls_b1   = (const float*)d_in[12];
    const float* cls_w2   = (const float*)d_in[13];
    const float* cls_b2   = (const float*)d_in[14];
    float* out = (float*)d_out;

    static int smem_set = 0;
    if (!smem_set) {
        cudaFuncSetAttribute(gemm_tc_kernel,
                             cudaFuncAttributeMaxDynamicSharedMemorySize, SMEM_BYTES);
        smem_set = 1;
    }

    void* p;
    cudaGetSymbolAddress(&p, g_bh);  const __nv_bfloat16* BH = (const __nv_bfloat16*)p;
    cudaGetSymbolAddress(&p, g_bl);  const __nv_bfloat16* BL = (const __nv_bfloat16*)p;

    // prep
    zero_misc_kernel<<<(NN * RR + 255) / 256, 256>>>();
    count_kernel<<<(EE + 255) / 256, 256>>>(ei, et);
    prefix_kernel<<<1, 1>>>();
    fill_kernel<<<(EE + 255) / 256, 256>>>(ei, et);
    prepB_kernel<<<(3 * KTOT * DD + 255) / 256, 256>>>(root_w, rel_w);
    initxa_kernel<<<(NN * 160 + 255) / 256, 256>>>(x);

    const int sblocks = (int)(((size_t)EE * 32 + 255) / 256);
    const int gblocks = (NN + 127) / 128;
    const int pblocks = (((NN + 31) / 32) * 32 + 255) / 256;

    // layer 0 (zeroes aggs for layer 1 in epilogue)
    scatter_kernel<<<sblocks, 256>>>();
    gemm_tc_kernel<<<gblocks, 256, SMEM_BYTES>>>(BH, BL, bias,
                                                 bn_gamma, bn_beta, bn_mean, bn_var, 0, 1);
    // layer 1 (zeroes aggs for layer 2)
    scatter_kernel<<<sblocks, 256>>>();
    gemm_tc_kernel<<<gblocks, 256, SMEM_BYTES>>>(BH + DD * KTOT, BL + DD * KTOT, bias + DD,
                                                 bn_gamma + DD, bn_beta + DD, bn_mean + DD,
                                                 bn_var + DD, 1, 1);
    // layer 2
    scatter_kernel<<<sblocks, 256>>>();
    gemm_tc_kernel<<<gblocks, 256, SMEM_BYTES>>>(BH + 2 * DD * KTOT, BL + 2 * DD * KTOT,
                                                 bias + 2 * DD,
                                                 bn_gamma, bn_beta, bn_mean, bn_var, 2, 0);

    // pool + head
    pool_kernel<<<pblocks, 256>>>(batch);
    head_kernel<<<GG, 64>>>(cls_w1, cls_b1, cls_w2, cls_b2, out);
}

// round 7
// speedup vs baseline: 2.5867x; 1.6954x over previous
#include <cuda_runtime.h>
#include <cuda_bf16.h>
#include <math.h>
#include <stdint.h>

// Problem constants
#define NN 100000
#define EE 600000
#define DD 128
#define RR 4
#define GG 256
#define CC 16
#define KTOT 640          // 128 (h) + 4*128 (per-relation aggregates)
#define NAGG 512          // agg cols
#define NB_SCAN 391       // ceil(NN/256)

// ---------------- device scratch ----------------
__device__ float          g_h0[(size_t)NN * DD];      // 51 MB
__device__ float          g_h1[(size_t)NN * DD];      // 51 MB
__device__ __nv_bfloat16  g_agg[(size_t)NN * NAGG];   // 102 MB
__device__ __nv_bfloat16  g_bh[3 * DD * KTOT];        // B hi bf16, [l][n][k]
__device__ __nv_bfloat16  g_bl[3 * DD * KTOT];        // B lo bf16
__device__ int    g_cnt[NN * RR];                     // per (dst,rel) in-degree
__device__ int    g_off[NN];                          // CSR row offsets (by dst)
__device__ int    g_fpos[NN];                         // fill tickets
__device__ int    g_bsum[512];                        // scan partials
__device__ int    g_eidx[EE];                         // packed (src<<2)|rel, dst-sorted
__device__ float  g_pool[GG * DD];
__device__ float  g_pcnt[GG];

// ---------------- helpers ----------------
__device__ __forceinline__ void red_add_v4(float* addr, float x, float y, float z, float w) {
    asm volatile("red.global.add.v4.f32 [%0], {%1,%2,%3,%4};"
                 :: "l"(addr), "f"(x), "f"(y), "f"(z), "f"(w) : "memory");
}
__device__ __forceinline__ float elu1(float v) { return v > 0.0f ? v : expm1f(v); }
__device__ __forceinline__ float bf16_round(float v) {
    return __bfloat162float(__float2bfloat16_rn(v));
}
// pack {lo, hi}: lower 16 bits = bf16(lo)
__device__ __forceinline__ uint32_t pack_bf16x2(float lo, float hi) {
    uint32_t r;
    asm("cvt.rn.bf16x2.f32 %0, %1, %2;" : "=r"(r) : "f"(hi), "f"(lo));
    return r;
}
__device__ __forceinline__ void mma_bf16(float* c, const uint32_t* a, uint32_t b0, uint32_t b1) {
    asm volatile("mma.sync.aligned.m16n8k16.row.col.f32.bf16.bf16.f32 "
                 "{%0,%1,%2,%3}, {%4,%5,%6,%7}, {%8,%9}, {%0,%1,%2,%3};"
                 : "+f"(c[0]), "+f"(c[1]), "+f"(c[2]), "+f"(c[3])
                 : "r"(a[0]), "r"(a[1]), "r"(a[2]), "r"(a[3]), "r"(b0), "r"(b1));
}
__device__ __forceinline__ void ldsm4(uint32_t* r, uint32_t addr) {
    asm volatile("ldmatrix.sync.aligned.m8n8.x4.shared.b16 {%0,%1,%2,%3}, [%4];"
                 : "=r"(r[0]), "=r"(r[1]), "=r"(r[2]), "=r"(r[3]) : "r"(addr));
}
__device__ __forceinline__ void cp16(uint32_t dst, const void* src) {
    asm volatile("cp.async.ca.shared.global [%0], [%1], 16;" :: "r"(dst), "l"(src));
}
__device__ __forceinline__ void cp_commit() { asm volatile("cp.async.commit_group;"); }
__device__ __forceinline__ void cp_wait0()  { asm volatile("cp.async.wait_group 0;"); }

// ---------------- prep kernels ----------------
__global__ void zero_misc_kernel() {
    int i = blockIdx.x * blockDim.x + threadIdx.x;
    if (i < NN * RR) g_cnt[i] = 0;
    if (i < NN)      g_fpos[i] = 0;
    if (i < GG * DD) g_pool[i] = 0.0f;
    if (i < GG)      g_pcnt[i] = 0.0f;
}

__global__ __launch_bounds__(256) void count_kernel(const int* __restrict__ ei,
                                                    const int* __restrict__ et) {
    int e = blockIdx.x * blockDim.x + threadIdx.x;
    if (e >= EE) return;
    atomicAdd(&g_cnt[ei[EE + e] * RR + et[e]], 1);
}

// block-level exclusive scan of per-dst degree (sum of 4 relation counts)
__global__ __launch_bounds__(256) void scan1_kernel() {
    __shared__ int sh[256];
    int i = blockIdx.x * 256 + threadIdx.x;
    int deg = 0;
    if (i < NN) {
        int4 c = *(const int4*)&g_cnt[4 * i];
        deg = c.x + c.y + c.z + c.w;
    }
    sh[threadIdx.x] = deg;
    __syncthreads();
    #pragma unroll
    for (int s = 1; s < 256; s <<= 1) {
        int t = (threadIdx.x >= s) ? sh[threadIdx.x - s] : 0;
        __syncthreads();
        sh[threadIdx.x] += t;
        __syncthreads();
    }
    if (i < NN) g_off[i] = sh[threadIdx.x] - deg;       // exclusive within block
    if (threadIdx.x == 255) g_bsum[blockIdx.x] = sh[255];
}

__global__ void scan2_kernel() {
    int run = 0;
    for (int b = 0; b < NB_SCAN; b++) { int t = g_bsum[b]; g_bsum[b] = run; run += t; }
}

__global__ __launch_bounds__(256) void scan3_kernel() {
    int i = blockIdx.x * 256 + threadIdx.x;
    if (i < NN) g_off[i] += g_bsum[blockIdx.x];
}

__global__ __launch_bounds__(256) void fill_kernel(const int* __restrict__ ei,
                                                   const int* __restrict__ et) {
    int e = blockIdx.x * blockDim.x + threadIdx.x;
    if (e >= EE) return;
    int s = ei[e], d = ei[EE + e], t = et[e];
    int pos = g_off[d] + atomicAdd(&g_fpos[d], 1);
    g_eidx[pos] = (s << 2) | t;
}

// transposed split-bf16 weights: Bt[l][n][k]
__global__ void prepB_kernel(const float* __restrict__ root_w, const float* __restrict__ rel_w) {
    int idx = blockIdx.x * blockDim.x + threadIdx.x;
    if (idx >= 3 * KTOT * DD) return;
    int l = idx / (KTOT * DD);
    int rem = idx - l * KTOT * DD;
    int k = rem / DD;
    int n = rem - k * DD;
    float b;
    if (k < DD) b = root_w[(size_t)l * DD * DD + k * DD + n];
    else {
        int r = (k - DD) >> 7, kk = (k - DD) & 127;
        b = rel_w[(((size_t)l * RR + r) * DD + kk) * DD + n];
    }
    __nv_bfloat16 hi = __float2bfloat16_rn(b);
    __nv_bfloat16 lo = __float2bfloat16_rn(b - __bfloat162float(hi));
    size_t o = (size_t)l * DD * KTOT + (size_t)n * KTOT + k;
    g_bh[o] = hi;
    g_bl[o] = lo;
}

// ---------------- gather: warp per dst, CSR edges, write agg (bf16) once ----------
__global__ __launch_bounds__(256) void gather_kernel(const float* __restrict__ hsrc) {
    int w = (blockIdx.x * blockDim.x + threadIdx.x) >> 5;
    int lane = threadIdx.x & 31;
    if (w >= NN) return;
    int off = g_off[w];
    int end = (w + 1 < NN) ? g_off[w + 1] : EE;

    float a0x = 0.f, a0y = 0.f, a0z = 0.f, a0w = 0.f;
    float a1x = 0.f, a1y = 0.f, a1z = 0.f, a1w = 0.f;
    float a2x = 0.f, a2y = 0.f, a2z = 0.f, a2w = 0.f;
    float a3x = 0.f, a3y = 0.f, a3z = 0.f, a3w = 0.f;

    for (int e = off; e < end; e++) {
        int pk = g_eidx[e];
        const float4 v = *(const float4*)(hsrc + (size_t)(pk >> 2) * DD + lane * 4);
        int r = pk & 3;
        if (r == 0)      { a0x += v.x; a0y += v.y; a0z += v.z; a0w += v.w; }
        else if (r == 1) { a1x += v.x; a1y += v.y; a1z += v.z; a1w += v.w; }
        else if (r == 2) { a2x += v.x; a2y += v.y; a2z += v.z; a2w += v.w; }
        else             { a3x += v.x; a3y += v.y; a3z += v.z; a3w += v.w; }
    }

    int4 c = *(const int4*)&g_cnt[4 * w];
    float w0 = 1.0f / (float)(c.x > 1 ? c.x : 1);
    float w1 = 1.0f / (float)(c.y > 1 ? c.y : 1);
    float w2 = 1.0f / (float)(c.z > 1 ? c.z : 1);
    float w3 = 1.0f / (float)(c.w > 1 ? c.w : 1);

    __nv_bfloat16* ag = g_agg + (size_t)w * NAGG + lane * 4;
    uint2 u;
    u.x = pack_bf16x2(a0x * w0, a0y * w0); u.y = pack_bf16x2(a0z * w0, a0w * w0);
    *(uint2*)(ag + 0 * DD) = u;
    u.x = pack_bf16x2(a1x * w1, a1y * w1); u.y = pack_bf16x2(a1z * w1, a1w * w1);
    *(uint2*)(ag + 1 * DD) = u;
    u.x = pack_bf16x2(a2x * w2, a2y * w2); u.y = pack_bf16x2(a2z * w2, a2w * w2);
    *(uint2*)(ag + 2 * DD) = u;
    u.x = pack_bf16x2(a3x * w3, a3y * w3); u.y = pack_bf16x2(a3z * w3, a3w * w3);
    *(uint2*)(ag + 3 * DD) = u;
}

// ---------------- GEMM: C[N,128] = [h | agg] x B, mixed precision ----------------
// h k-chunks (kc 0..3): fp32 -> bf16 hi/lo split, 3-term mma.
// agg k-chunks (kc 4..19): bf16 direct cp.async as A-hi, 2-term mma.
// Block 128x128, 8 warps (2x4), warp tile 64x32. Smem rows padded to 80B.
// mode 0: bias+BN+ELU | 1: bias+resid+BN+ELU | 2: bias+resid
#define STG_STRIDE 10240
#define AH_OFF 0
#define AL_OFF 20480
#define BH_OFF 40960
#define BL_OFF 61440
#define SMEM_BYTES 81920

__global__ __launch_bounds__(256) void gemm_tc_kernel(
    const float* __restrict__ hsrc, float* __restrict__ hdst,
    const __nv_bfloat16* __restrict__ Bhg, const __nv_bfloat16* __restrict__ Blg,
    const float* __restrict__ bias,
    const float* __restrict__ gamma, const float* __restrict__ beta,
    const float* __restrict__ mean, const float* __restrict__ var,
    int mode)
{
    extern __shared__ char smc[];
    const uint32_t smb = (uint32_t)__cvta_generic_to_shared(smc);

    const int tid = threadIdx.x;
    const int warp = tid >> 5, lane = tid & 31;
    const int wm = warp >> 2, wn = warp & 3;
    const int row0 = blockIdx.x * 128;

    float acc[4][4][4];
    #pragma unroll
    for (int i = 0; i < 4; i++)
        #pragma unroll
        for (int j = 0; j < 4; j++)
            #pragma unroll
            for (int k = 0; k < 4; k++) acc[i][j][k] = 0.0f;

    // ldmatrix per-thread bases
    uint32_t a_addr[4];
    #pragma unroll
    for (int mt = 0; mt < 4; mt++) {
        int m = wm * 64 + mt * 16 + (lane & 15);
        a_addr[mt] = smb + AH_OFF + m * 80 + (lane >> 4) * 16;
    }
    uint32_t b_addr[2];
    #pragma unroll
    for (int p = 0; p < 2; p++) {
        int n = wn * 32 + p * 16 + (lane & 7) + (lane >> 4) * 8;
        b_addr[p] = smb + BH_OFF + n * 80 + ((lane >> 3) & 1) * 16;
    }

    // loader geometry: lc = 16B chunk (0..3), lr = row (0..63), rows lr & lr+64
    const int lc = tid & 3;
    const int lr = tid >> 2;
    float4 areg[4];

    #define LDGA(kc) {                                                            \
        int _k0 = (kc) * 32 + lc * 8;                                             \
        _Pragma("unroll")                                                         \
        for (int i = 0; i < 2; i++) {                                             \
            int grow = row0 + lr + 64 * i;                                        \
            if (grow >= NN) grow = NN - 1;                                        \
            areg[2*i]   = *(const float4*)(hsrc + (size_t)grow * DD + _k0);       \
            areg[2*i+1] = *(const float4*)(hsrc + (size_t)grow * DD + _k0 + 4);   \
        }                                                                         \
    }
    #define STSA(b) {                                                             \
        _Pragma("unroll")                                                         \
        for (int i = 0; i < 2; i++) {                                             \
            float4 v0 = areg[2*i], v1 = areg[2*i+1];                              \
            uint4 uh;                                                             \
            uh.x = pack_bf16x2(v0.x, v0.y);                                       \
            uh.y = pack_bf16x2(v0.z, v0.w);                                       \
            uh.z = pack_bf16x2(v1.x, v1.y);                                       \
            uh.w = pack_bf16x2(v1.z, v1.w);                                       \
            uint4 ul;                                                             \
            ul.x = pack_bf16x2(v0.x - bf16_round(v0.x), v0.y - bf16_round(v0.y)); \
            ul.y = pack_bf16x2(v0.z - bf16_round(v0.z), v0.w - bf16_round(v0.w)); \
            ul.z = pack_bf16x2(v1.x - bf16_round(v1.x), v1.y - bf16_round(v1.y)); \
            ul.w = pack_bf16x2(v1.z - bf16_round(v1.z), v1.w - bf16_round(v1.w)); \
            uint32_t off = (lr + 64*i) * 80u + lc * 16u + (b) * STG_STRIDE;       \
            *(uint4*)(smc + AH_OFF + off) = uh;                                   \
            *(uint4*)(smc + AL_OFF + off) = ul;                                   \
        }                                                                         \
    }
    #define CPA(kc, b) {                                                          \
        int _k0 = ((kc) - 4) * 32 + lc * 8;                                       \
        _Pragma("unroll")                                                         \
        for (int i = 0; i < 2; i++) {                                             \
            int grow = row0 + lr + 64 * i;                                        \
            if (grow >= NN) grow = NN - 1;                                        \
            uint32_t off = (lr + 64*i) * 80u + lc * 16u + (b) * STG_STRIDE;       \
            cp16(smb + AH_OFF + off, g_agg + (size_t)grow * NAGG + _k0);          \
        }                                                                         \
    }
    #define CPB(kc, b) {                                                          \
        int _k0 = (kc) * 32 + lc * 8;                                             \
        _Pragma("unroll")                                                         \
        for (int i = 0; i < 2; i++) {                                             \
            int n = lr + 64 * i;                                                  \
            uint32_t off = n * 80u + lc * 16u + (b) * STG_STRIDE;                 \
            cp16(smb + BH_OFF + off, Bhg + (size_t)n * KTOT + _k0);               \
            cp16(smb + BL_OFF + off, Blg + (size_t)n * KTOT + _k0);               \
        }                                                                         \
    }
    #define COMPUTE3(b) {                                                         \
        uint32_t bo = (b) * (uint32_t)STG_STRIDE;                                 \
        _Pragma("unroll")                                                         \
        for (int ks = 0; ks < 2; ks++) {                                          \
            uint32_t ah[4][4], al[4][4], bh[2][4], bl[2][4];                      \
            _Pragma("unroll")                                                     \
            for (int mt = 0; mt < 4; mt++) {                                      \
                ldsm4(ah[mt], a_addr[mt] + bo + ks * 32);                         \
                ldsm4(al[mt], a_addr[mt] + (AL_OFF - AH_OFF) + bo + ks * 32);     \
            }                                                                     \
            _Pragma("unroll")                                                     \
            for (int p = 0; p < 2; p++) {                                         \
                ldsm4(bh[p], b_addr[p] + bo + ks * 32);                           \
                ldsm4(bl[p], b_addr[p] + (BL_OFF - BH_OFF) + bo + ks * 32);       \
            }                                                                     \
            _Pragma("unroll")                                                     \
            for (int mt = 0; mt < 4; mt++)                                        \
                _Pragma("unroll")                                                 \
                for (int nt = 0; nt < 4; nt++) {                                  \
                    int p = nt >> 1, ix = (nt & 1) * 2;                           \
                    mma_bf16(acc[mt][nt], ah[mt], bh[p][ix], bh[p][ix+1]);        \
                    mma_bf16(acc[mt][nt], ah[mt], bl[p][ix], bl[p][ix+1]);        \
                    mma_bf16(acc[mt][nt], al[mt], bh[p][ix], bh[p][ix+1]);        \
                }                                                                 \
        }                                                                         \
    }
    #define COMPUTE2(b) {                                                         \
        uint32_t bo = (b) * (uint32_t)STG_STRIDE;                                 \
        _Pragma("unroll")                                                         \
        for (int ks = 0; ks < 2; ks++) {                                          \
            uint32_t ah[4][4], bh[2][4], bl[2][4];                                \
            _Pragma("unroll")                                                     \
            for (int mt = 0; mt < 4; mt++)                                        \
                ldsm4(ah[mt], a_addr[mt] + bo + ks * 32);                         \
            _Pragma("unroll")                                                     \
            for (int p = 0; p < 2; p++) {                                         \
                ldsm4(bh[p], b_addr[p] + bo + ks * 32);                           \
                ldsm4(bl[p], b_addr[p] + (BL_OFF - BH_OFF) + bo + ks * 32);       \
            }                                                                     \
            _Pragma("unroll")                                                     \
            for (int mt = 0; mt < 4; mt++)                                        \
                _Pragma("unroll")                                                 \
                for (int nt = 0; nt < 4; nt++) {                                  \
                    int p = nt >> 1, ix = (nt & 1) * 2;                           \
                    mma_bf16(acc[mt][nt], ah[mt], bh[p][ix], bh[p][ix+1]);        \
                    mma_bf16(acc[mt][nt], ah[mt], bl[p][ix], bl[p][ix+1]);        \
                }                                                                 \
        }                                                                         \
    }

    // prologue: stage kc=0 (h chunk)
    LDGA(0);
    CPB(0, 0); cp_commit();
    STSA(0);
    cp_wait0();
    __syncthreads();

    int buf = 0;
    // h-phase: kc = 0..3 (3-term)
    #pragma unroll 1
    for (int kc = 0; kc < 4; kc++) {
        if (kc < 3) { LDGA(kc + 1); CPB(kc + 1, buf ^ 1); cp_commit(); }
        else        { CPA(4, buf ^ 1); CPB(4, buf ^ 1); cp_commit(); }
        COMPUTE3(buf);
        if (kc < 3) STSA(buf ^ 1);
        cp_wait0();
        __syncthreads();
        buf ^= 1;
    }
    // agg-phase: kc = 4..19 (2-term, A-hi direct from agg)
    #pragma unroll 1
    for (int kc = 4; kc < 20; kc++) {
        if (kc < 19) { CPA(kc + 1, buf ^ 1); CPB(kc + 1, buf ^ 1); cp_commit(); }
        COMPUTE2(buf);
        if (kc < 19) cp_wait0();
        __syncthreads();
        buf ^= 1;
    }

    // fused epilogue -> hdst
    #pragma unroll
    for (int nt = 0; nt < 4; nt++) {
        int col = wn * 32 + nt * 8 + ((lane & 3) << 1);
        float b0 = bias[col], b1 = bias[col + 1];
        float g0 = 0.f, g1 = 0.f, be0 = 0.f, be1 = 0.f, mu0 = 0.f, mu1 = 0.f, rs0 = 0.f, rs1 = 0.f;
        if (mode <= 1) {
            g0 = gamma[col]; g1 = gamma[col + 1];
            be0 = beta[col]; be1 = beta[col + 1];
            mu0 = mean[col]; mu1 = mean[col + 1];
            rs0 = rsqrtf(var[col] + 1e-5f); rs1 = rsqrtf(var[col + 1] + 1e-5f);
        }
        #pragma unroll
        for (int mt = 0; mt < 4; mt++) {
            #pragma unroll
            for (int half = 0; half < 2; half++) {
                int row = row0 + wm * 64 + mt * 16 + (lane >> 2) + half * 8;
                if (row >= NN) continue;
                float v0 = acc[mt][nt][half * 2 + 0] + b0;
                float v1 = acc[mt][nt][half * 2 + 1] + b1;
                if (mode >= 1) {
                    const float* rp = hsrc + (size_t)row * DD + col;
                    v0 += rp[0]; v1 += rp[1];
                }
                if (mode <= 1) {
                    v0 = elu1((v0 - mu0) * rs0 * g0 + be0);
                    v1 = elu1((v1 - mu1) * rs1 * g1 + be1);
                }
                float* hp = hdst + (size_t)row * DD + col;
                hp[0] = v0; hp[1] = v1;
            }
        }
    }
    #undef LDGA
    #undef STSA
    #undef CPA
    #undef CPB
    #undef COMPUTE3
    #undef COMPUTE2
}

// ---------------- pooling (batch sorted) ----------------
__global__ __launch_bounds__(256) void pool_kernel(const float* __restrict__ h,
                                                   const int* __restrict__ batch) {
    int warp = (blockIdx.x * blockDim.x + threadIdx.x) >> 5;
    int lane = threadIdx.x & 31;
    int n0 = warp * 32;
    if (n0 >= NN) return;
    int nend = n0 + 32 < NN ? n0 + 32 : NN;

    float4 acc = make_float4(0.f, 0.f, 0.f, 0.f);
    int cur = batch[n0];
    int cnt = 0;
    for (int n = n0; n < nend; n++) {
        int b = batch[n];
        if (b != cur) {
            red_add_v4(g_pool + cur * DD + lane * 4, acc.x, acc.y, acc.z, acc.w);
            if (lane == 0) atomicAdd(&g_pcnt[cur], (float)cnt);
            acc = make_float4(0.f, 0.f, 0.f, 0.f);
            cnt = 0;
            cur = b;
        }
        float4 v = *(const float4*)(h + (size_t)n * DD + lane * 4);
        acc.x += v.x; acc.y += v.y; acc.z += v.z; acc.w += v.w;
        cnt++;
    }
    red_add_v4(g_pool + cur * DD + lane * 4, acc.x, acc.y, acc.z, acc.w);
    if (lane == 0) atomicAdd(&g_pcnt[cur], (float)cnt);
}

// ---------------- classifier head ----------------
__global__ __launch_bounds__(64) void head_kernel(
    const float* __restrict__ W1, const float* __restrict__ b1,
    const float* __restrict__ W2, const float* __restrict__ b2,
    float* __restrict__ out)
{
    int g = blockIdx.x;
    __shared__ float p[DD];
    __shared__ float z[64];
    __shared__ float lg[CC];

    float inv = 1.0f / fmaxf(g_pcnt[g], 1.0f);
    for (int d = threadIdx.x; d < DD; d += 64) p[d] = g_pool[g * DD + d] * inv;
    __syncthreads();

    int j = threadIdx.x;
    float s = b1[j];
    #pragma unroll 4
    for (int d = 0; d < DD; d++) s += p[d] * W1[d * 64 + j];
    z[j] = elu1(s);
    __syncthreads();

    if (j < CC) {
        float t = b2[j];
        #pragma unroll 4
        for (int k = 0; k < 64; k++) t += z[k] * W2[k * CC + j];
        lg[j] = t;
    }
    __syncthreads();

    if (j < CC) {
        float m = -1e30f;
        #pragma unroll
        for (int c = 0; c < CC; c++) m = fmaxf(m, lg[c]);
        float se = 0.0f;
        #pragma unroll
        for (int c = 0; c < CC; c++) se += expf(lg[c] - m);
        out[g * CC + j] = lg[j] - m - logf(se);
    }
}

// ---------------- launch ----------------
extern "C" void kernel_launch(void* const* d_in, const int* in_sizes, int n_in,
                              void* d_out, int out_size) {
    const float* x        = (const float*)d_in[0];
    const int*   ei       = (const int*)d_in[1];
    const int*   et       = (const int*)d_in[2];
    const int*   batch    = (const int*)d_in[3];
    const float* rel_w    = (const float*)d_in[4];
    const float* root_w   = (const float*)d_in[5];
    const float* bias     = (const float*)d_in[6];
    const float* bn_gamma = (const float*)d_in[7];
    const float* bn_beta  = (const float*)d_in[8];
    const float* bn_mean  = (const float*)d_in[9];
    const float* bn_var   = (const float*)d_in[10];
    const float* cls_w1   = (const float*)d_in[11];
    const float* cls_b1   = (const float*)d_in[12];
    const float* cls_w2   = (const float*)d_in[13];
    const float* cls_b2   = (const float*)d_in[14];
    float* out = (float*)d_out;

    static int smem_set = 0;
    if (!smem_set) {
        cudaFuncSetAttribute(gemm_tc_kernel,
                             cudaFuncAttributeMaxDynamicSharedMemorySize, SMEM_BYTES);
        smem_set = 1;
    }

    void* p;
    cudaGetSymbolAddress(&p, g_bh);  const __nv_bfloat16* BH = (const __nv_bfloat16*)p;
    cudaGetSymbolAddress(&p, g_bl);  const __nv_bfloat16* BL = (const __nv_bfloat16*)p;
    cudaGetSymbolAddress(&p, g_h0);  float* H0 = (float*)p;
    cudaGetSymbolAddress(&p, g_h1);  float* H1 = (float*)p;

    // prep: counts -> CSR scan -> dst-sorted edge list -> split weights
    zero_misc_kernel<<<(NN * RR + 255) / 256, 256>>>();
    count_kernel<<<(EE + 255) / 256, 256>>>(ei, et);
    scan1_kernel<<<NB_SCAN, 256>>>();
    scan2_kernel<<<1, 1>>>();
    scan3_kernel<<<NB_SCAN, 256>>>();
    fill_kernel<<<(EE + 255) / 256, 256>>>(ei, et);
    prepB_kernel<<<(3 * KTOT * DD + 255) / 256, 256>>>(root_w, rel_w);

    const int gablocks = (NN * 32 + 255) / 256;   // gather: warp per dst
    const int gmblocks = (NN + 127) / 128;
    const int pblocks  = (((NN + 31) / 32) * 32 + 255) / 256;

    // layer 0: x -> h0
    gather_kernel<<<gablocks, 256>>>(x);
    gemm_tc_kernel<<<gmblocks, 256, SMEM_BYTES>>>(x, H0, BH, BL, bias,
                                                  bn_gamma, bn_beta, bn_mean, bn_var, 0);
    // layer 1: h0 -> h1 (residual + BN1 + ELU)
    gather_kernel<<<gablocks, 256>>>(H0);
    gemm_tc_kernel<<<gmblocks, 256, SMEM_BYTES>>>(H0, H1, BH + DD * KTOT, BL + DD * KTOT,
                                                  bias + DD, bn_gamma + DD, bn_beta + DD,
                                                  bn_mean + DD, bn_var + DD, 1);
    // layer 2: h1 -> h0 (residual only)
    gather_kernel<<<gablocks, 256>>>(H1);
    gemm_tc_kernel<<<gmblocks, 256, SMEM_BYTES>>>(H1, H0, BH + 2 * DD * KTOT,
                                                  BL + 2 * DD * KTOT, bias + 2 * DD,
                                                  bn_gamma, bn_beta, bn_mean, bn_var, 2);

    // pool + head
    pool_kernel<<<pblocks, 256>>>(H0, batch);
    head_kernel<<<GG, 64>>>(cls_w1, cls_b1, cls_w2, cls_b2, out);
}